// round 5
// baseline (speedup 1.0000x reference)
#include <cuda_runtime.h>

// Algebraic reduction of the reference (verified R2-R4, rel_err ~1.4e-7):
//   tr = (op - op) * weight == 0 exactly  =>  real_sum == 0  =>
//   out[b] = relu(relu(bf1) @ Wf2^T + bf2) @ Wf3^T + bf3   (same scalar, all b)
// Live inputs: bf1, Wf2(128x128), bf2, Wf3, bf3 — located by anchoring on
// Wf1's unique element count (128*32768) in in_sizes.
//
// R5 change: 512 threads (16 warps) instead of 1024 — halves warp
// dispatch/drain at the single-block overhead floor. 4 threads/row, 32
// elements each (16 independent LDG.128 per thread, one latency window,
// 4-way FMA ILP). Reduce tail shortened by one shfl level.

#define PF 128

__global__ __launch_bounds__(512, 1)
void TF2N_35347580846484_kernel(const float* __restrict__ bf1,
                                const float* __restrict__ Wf2,
                                const float* __restrict__ bf2,
                                const float* __restrict__ Wf3,
                                const float* __restrict__ bf3,
                                float* __restrict__ out) {
    __shared__ float wsum[16];         // per-warp partial sums

    const int t = threadIdx.x;
    const int r = t >> 2;              // output row 0..127
    const int c = t & 3;               // 32-col chunk within the row

    // Issue ALL global loads up front; every one is independent.
    const float4* __restrict__ wp =
        reinterpret_cast<const float4*>(Wf2 + r * PF + c * 32);
    const float4* __restrict__ zp =
        reinterpret_cast<const float4*>(bf1 + c * 32);

    float4 w[8], a[8];
#pragma unroll
    for (int k = 0; k < 8; ++k) w[k] = wp[k];
#pragma unroll
    for (int k = 0; k < 8; ++k) a[k] = zp[k];
    const float b2  = bf2[r];
    const float w3r = Wf3[r];
    const float b3  = bf3[0];

    // relu(bf1) in registers
#pragma unroll
    for (int k = 0; k < 8; ++k) {
        a[k].x = fmaxf(a[k].x, 0.0f);
        a[k].y = fmaxf(a[k].y, 0.0f);
        a[k].z = fmaxf(a[k].z, 0.0f);
        a[k].w = fmaxf(a[k].w, 0.0f);
    }

    // 32-element partial dot with 4 independent accumulators.
    float s0 = 0.f, s1 = 0.f, s2 = 0.f, s3 = 0.f;
#pragma unroll
    for (int k = 0; k < 8; ++k) {
        s0 = fmaf(w[k].x, a[k].x, s0);
        s1 = fmaf(w[k].y, a[k].y, s1);
        s2 = fmaf(w[k].z, a[k].z, s2);
        s3 = fmaf(w[k].w, a[k].w, s3);
    }
    float acc = (s0 + s1) + (s2 + s3);

    // Reduce the 4 chunk-partials of this row (lanes differ in low 2 bits).
    acc += __shfl_xor_sync(0xffffffffu, acc, 1);
    acc += __shfl_xor_sync(0xffffffffu, acc, 2);

    // Row leader folds in bias + relu + Wf3 weight; others contribute 0.
    float contrib = (c == 0) ? fmaxf(acc + b2, 0.0f) * w3r : 0.0f;

    // Sum the 8 row-contributions within this warp (leaders at lanes 0,4,..).
    contrib += __shfl_xor_sync(0xffffffffu, contrib, 4);
    contrib += __shfl_xor_sync(0xffffffffu, contrib, 8);
    contrib += __shfl_xor_sync(0xffffffffu, contrib, 16);

    if ((t & 31) == 0) wsum[t >> 5] = contrib;
    __syncthreads();

    // Final 16-value reduce in warp 0; broadcast scalar to all B=32 outputs.
    if (t < 32) {
        float s = (t < 16) ? wsum[t] : 0.0f;
        s += __shfl_xor_sync(0xffffffffu, s, 1);
        s += __shfl_xor_sync(0xffffffffu, s, 2);
        s += __shfl_xor_sync(0xffffffffu, s, 4);
        s += __shfl_xor_sync(0xffffffffu, s, 8);
        s += __shfl_xor_sync(0xffffffffu, s, 16);
        s += b3;
        out[t] = s;
    }
}

extern "C" void kernel_launch(void* const* d_in, const int* in_sizes, int n_in,
                              void* d_out, int out_size) {
    (void)out_size;

    // Anchor: Wf1 has 128*32768 = 4194304 elements, unique by far.
    int wf1 = 26;
    for (int k = 0; k < n_in; ++k) {
        if (in_sizes[k] == 128 * 32768) { wf1 = k; break; }
    }

    const float* bf1 = (const float*)d_in[wf1 + 1];
    const float* Wf2 = (const float*)d_in[wf1 + 2];
    const float* bf2 = (const float*)d_in[wf1 + 3];
    const float* Wf3 = (const float*)d_in[wf1 + 4];
    const float* bf3 = (const float*)d_in[wf1 + 5];
    float* out = (float*)d_out;

    TF2N_35347580846484_kernel<<<1, 512>>>(bf1, Wf2, bf2, Wf3, bf3, out);
}

// round 8
// speedup vs baseline: 1.3077x; 1.3077x over previous
#include <cuda_runtime.h>

// Algebraic reduction of the reference (verified R2-R5, rel_err ~1e-7):
//   tr = (op - op) * weight == 0 exactly  =>  real_sum == 0  =>
//   out[b] = relu(relu(bf1) @ Wf2^T + bf2) @ Wf3^T + bf3   (same scalar, all b)
// Live inputs: bf1, Wf2(128x128), bf2, Wf3, bf3 — located by anchoring on
// Wf1's unique element count (128*32768) in in_sizes.
//
// R8: R4's winning shape (1024 thr, 8 thr/row, 8x LDG.128/thread, one
// concurrent load window, no pre-FMA barrier) + predicate-free row fold.
// R7 bug post-mortem: the *0.125 compensation was wrong — the xor-8/16
// butterfly sums across the 4 ROW GROUPS only (bits 3-4), never over the
// 8-lane replication (bits 0-2), so no /8 is needed. Every lane of a row
// group holds the identical folded value; the cross-group butterfly then
// yields the exact 4-row sum on every lane. No lane select required.

#define PF 128

__global__ __launch_bounds__(1024, 1)
void TF2N_35347580846484_kernel(const float* __restrict__ bf1,
                                const float* __restrict__ Wf2,
                                const float* __restrict__ bf2,
                                const float* __restrict__ Wf3,
                                const float* __restrict__ bf3,
                                float* __restrict__ out) {
    __shared__ float wsum[32];         // per-warp partial sums

    const int t = threadIdx.x;
    const int r = t >> 3;              // output row 0..127
    const int c = t & 7;               // 16-col chunk within the row

    // Issue ALL global loads up front; every one is independent.
    const float4* __restrict__ wp =
        reinterpret_cast<const float4*>(Wf2 + r * PF + c * 16);
    const float4* __restrict__ zp =
        reinterpret_cast<const float4*>(bf1 + c * 16);
    const float4 w0 = wp[0];
    const float4 w1 = wp[1];
    const float4 w2 = wp[2];
    const float4 w3 = wp[3];
    float4 a0 = zp[0];
    float4 a1 = zp[1];
    float4 a2 = zp[2];
    float4 a3 = zp[3];
    const float b2  = bf2[r];
    const float w3r = Wf3[r];
    const float b3  = bf3[0];

    // relu(bf1) in registers
    a0.x = fmaxf(a0.x, 0.0f); a0.y = fmaxf(a0.y, 0.0f);
    a0.z = fmaxf(a0.z, 0.0f); a0.w = fmaxf(a0.w, 0.0f);
    a1.x = fmaxf(a1.x, 0.0f); a1.y = fmaxf(a1.y, 0.0f);
    a1.z = fmaxf(a1.z, 0.0f); a1.w = fmaxf(a1.w, 0.0f);
    a2.x = fmaxf(a2.x, 0.0f); a2.y = fmaxf(a2.y, 0.0f);
    a2.z = fmaxf(a2.z, 0.0f); a2.w = fmaxf(a2.w, 0.0f);
    a3.x = fmaxf(a3.x, 0.0f); a3.y = fmaxf(a3.y, 0.0f);
    a3.z = fmaxf(a3.z, 0.0f); a3.w = fmaxf(a3.w, 0.0f);

    // 16-element partial dot: Wf2[r, c*16 .. c*16+15] . relu(bf1)[c*16..]
    float acc;
    acc = w0.x * a0.x;
    acc = fmaf(w0.y, a0.y, acc);
    acc = fmaf(w0.z, a0.z, acc);
    acc = fmaf(w0.w, a0.w, acc);
    acc = fmaf(w1.x, a1.x, acc);
    acc = fmaf(w1.y, a1.y, acc);
    acc = fmaf(w1.z, a1.z, acc);
    acc = fmaf(w1.w, a1.w, acc);
    acc = fmaf(w2.x, a2.x, acc);
    acc = fmaf(w2.y, a2.y, acc);
    acc = fmaf(w2.z, a2.z, acc);
    acc = fmaf(w2.w, a2.w, acc);
    acc = fmaf(w3.x, a3.x, acc);
    acc = fmaf(w3.y, a3.y, acc);
    acc = fmaf(w3.z, a3.z, acc);
    acc = fmaf(w3.w, a3.w, acc);

    // Reduce the 8 chunk-partials of this row; all 8 lanes end with the sum.
    acc += __shfl_xor_sync(0xffffffffu, acc, 1);
    acc += __shfl_xor_sync(0xffffffffu, acc, 2);
    acc += __shfl_xor_sync(0xffffffffu, acc, 4);

    // Every lane of the row group folds bias + relu + Wf3 weight (identical
    // value on all 8 lanes). The cross-group butterfly below sums one
    // representative per row group at each lane position -> exact 4-row sum.
    float contrib = fmaxf(acc + b2, 0.0f) * w3r;

    // Sum the 4 row-groups of this warp (butterfly over bits 3-4 only).
    contrib += __shfl_xor_sync(0xffffffffu, contrib, 8);
    contrib += __shfl_xor_sync(0xffffffffu, contrib, 16);

    if ((t & 31) == 0) wsum[t >> 5] = contrib;
    __syncthreads();

    // Final 32-value reduce in warp 0; broadcast scalar to all B=32 outputs.
    if (t < 32) {
        float s = wsum[t];
#pragma unroll
        for (int o = 16; o > 0; o >>= 1)
            s += __shfl_xor_sync(0xffffffffu, s, o);
        s += b3;
        out[t] = s;
    }
}

extern "C" void kernel_launch(void* const* d_in, const int* in_sizes, int n_in,
                              void* d_out, int out_size) {
    (void)out_size;

    // Anchor: Wf1 has 128*32768 = 4194304 elements, unique by far.
    int wf1 = 26;
    for (int k = 0; k < n_in; ++k) {
        if (in_sizes[k] == 128 * 32768) { wf1 = k; break; }
    }

    const float* bf1 = (const float*)d_in[wf1 + 1];
    const float* Wf2 = (const float*)d_in[wf1 + 2];
    const float* bf2 = (const float*)d_in[wf1 + 3];
    const float* Wf3 = (const float*)d_in[wf1 + 4];
    const float* bf3 = (const float*)d_in[wf1 + 5];
    float* out = (float*)d_out;

    TF2N_35347580846484_kernel<<<1, 1024>>>(bf1, Wf2, bf2, Wf3, bf3, out);
}